// round 2
// baseline (speedup 1.0000x reference)
#include <cuda_runtime.h>
#include <math.h>

#define NUM_USERS 100000
#define NUM_ITEMS 50000
#define N_NODES   (NUM_USERS + NUM_ITEMS)   // 150000
#define LATENT    64
#define N_EDGES   2400000
#define BATCH     16384
#define VEC       (LATENT / 4)              // 16 float4 per node row
#define NODE_F4   (N_NODES * VEC)           // 2.4M float4 elements

// Scratch: ping-pong buffers + accumulator (38.4 MB each). Static device
// globals — no runtime allocation, graph-capture safe.
__device__ float g_A[N_NODES * LATENT];
__device__ float g_B[N_NODES * LATENT];
__device__ float g_acc[N_NODES * LATENT];

// ---------------------------------------------------------------------------
// init: A = concat(user_emb, item_emb); acc = A; B = 0
// ---------------------------------------------------------------------------
__global__ void init_kernel(const float4* __restrict__ uemb,
                            const float4* __restrict__ iemb)
{
    const int ucnt = NUM_USERS * VEC;
    for (int i = blockIdx.x * blockDim.x + threadIdx.x;
         i < NODE_F4; i += gridDim.x * blockDim.x)
    {
        float4 v = (i < ucnt) ? uemb[i] : iemb[i - ucnt];
        ((float4*)g_A)[i]   = v;
        ((float4*)g_acc)[i] = v;
        ((float4*)g_B)[i]   = make_float4(0.f, 0.f, 0.f, 0.f);
    }
}

// ---------------------------------------------------------------------------
// SPMM scatter: y[row] += val * x[col].  One thread per (edge, float4-chunk).
// 16 consecutive threads share one edge: edge-metadata loads are warp-
// broadcast, the x[col] gather is 2 contiguous 128B lines, and the reduction
// is a coalesced 256B vector-atomic burst.
// dir==0: A -> B ; dir==1: B -> A
// ---------------------------------------------------------------------------
__global__ void spmm_scatter(const int*   __restrict__ rows,
                             const int*   __restrict__ cols,
                             const float* __restrict__ vals,
                             int dir)
{
    const float4* __restrict__ x = (const float4*)(dir ? g_B : g_A);
    float4* y = (float4*)(dir ? g_A : g_B);

    const unsigned int total = (unsigned int)N_EDGES * VEC;   // 38.4M
    for (unsigned int i = blockIdx.x * blockDim.x + threadIdx.x;
         i < total; i += gridDim.x * blockDim.x)
    {
        unsigned int e = i >> 4;
        unsigned int c = i & 15u;

        int   r   = rows[e];
        int   col = cols[e];
        float v   = vals[e];

        float4 xv = x[col * VEC + c];
        float4 a  = make_float4(v * xv.x, v * xv.y, v * xv.z, v * xv.w);

        float4* p = &y[r * VEC + c];
        asm volatile("red.global.add.v4.f32 [%0], {%1, %2, %3, %4};"
                     :: "l"(p), "f"(a.x), "f"(a.y), "f"(a.z), "f"(a.w)
                     : "memory");
    }
}

// ---------------------------------------------------------------------------
// addzero: acc += (just-produced layer); zero the other buffer so it is
// ready as the next layer's destination.
// d==0: acc += B, A = 0 ; d==1: acc += A, B = 0
// ---------------------------------------------------------------------------
__global__ void addzero_kernel(int d)
{
    const float4* __restrict__ s = (const float4*)(d ? g_A : g_B);
    float4* z = (float4*)(d ? g_B : g_A);
    for (int i = blockIdx.x * blockDim.x + threadIdx.x;
         i < NODE_F4; i += gridDim.x * blockDim.x)
    {
        float4 acc = ((float4*)g_acc)[i];
        float4 sv  = s[i];
        acc.x += sv.x; acc.y += sv.y; acc.z += sv.z; acc.w += sv.w;
        ((float4*)g_acc)[i] = acc;
        z[i] = make_float4(0.f, 0.f, 0.f, 0.f);
    }
}

// ---------------------------------------------------------------------------
// MLP head: one warp per sample.
//   v  = 0.25 * concat(acc[user], acc[NUM_USERS+item])   (128)
//   h0 = relu(v @ W0 + b0)    (64)
//   h1 = relu(h0 @ W1 + b1)   (32)
//   out = sigmoid(h1 @ Wa + ba)
// Weight reads are coalesced across lanes; the ~41 KB weight set stays
// L1/L2-resident across the whole batch.
// ---------------------------------------------------------------------------
__global__ void mlp_kernel(const int*   __restrict__ users,
                           const int*   __restrict__ items,
                           const float* __restrict__ W0,
                           const float* __restrict__ b0,
                           const float* __restrict__ W1,
                           const float* __restrict__ b1,
                           const float* __restrict__ Wa,
                           const float* __restrict__ ba,
                           float* __restrict__ out)
{
    __shared__ float sv[8][128];
    __shared__ float sh0[8][64];

    int w    = threadIdx.x >> 5;
    int lane = threadIdx.x & 31;
    int s    = blockIdx.x * 8 + w;
    if (s >= BATCH) return;

    int u  = users[s];
    int it = items[s];

    const float* __restrict__ urow = g_acc + u * LATENT;
    const float* __restrict__ irow = g_acc + (NUM_USERS + it) * LATENT;
    #pragma unroll
    for (int k = lane; k < 64; k += 32) {
        sv[w][k]      = 0.25f * urow[k];
        sv[w][64 + k] = 0.25f * irow[k];
    }
    __syncwarp();

    // layer 0: 128 -> 64, each lane computes outputs {lane, lane+32}
    float a0 = b0[lane];
    float a1 = b0[lane + 32];
    #pragma unroll 8
    for (int k = 0; k < 128; k++) {
        float vk = sv[w][k];
        a0 = fmaf(vk, W0[k * 64 + lane],      a0);
        a1 = fmaf(vk, W0[k * 64 + lane + 32], a1);
    }
    sh0[w][lane]      = fmaxf(a0, 0.f);
    sh0[w][lane + 32] = fmaxf(a1, 0.f);
    __syncwarp();

    // layer 1: 64 -> 32, lane computes output `lane`
    float h1 = b1[lane];
    #pragma unroll 8
    for (int k = 0; k < 64; k++)
        h1 = fmaf(sh0[w][k], W1[k * 32 + lane], h1);
    h1 = fmaxf(h1, 0.f);

    // logit: 32 -> 1, warp reduce
    float t = h1 * Wa[lane];
    #pragma unroll
    for (int off = 16; off > 0; off >>= 1)
        t += __shfl_down_sync(0xffffffffu, t, off);

    if (lane == 0) {
        float logit = t + ba[0];
        out[s] = 1.0f / (1.0f + __expf(-logit));
    }
}

// ---------------------------------------------------------------------------
extern "C" void kernel_launch(void* const* d_in, const int* in_sizes, int n_in,
                              void* d_out, int out_size)
{
    const int*   users = (const int*)  d_in[0];
    const int*   items = (const int*)  d_in[1];
    const int*   rows  = (const int*)  d_in[2];
    const int*   cols  = (const int*)  d_in[3];
    const float* vals  = (const float*)d_in[4];
    const float* uemb  = (const float*)d_in[5];
    const float* iemb  = (const float*)d_in[6];
    const float* W0    = (const float*)d_in[7];
    const float* b0    = (const float*)d_in[8];
    const float* W1    = (const float*)d_in[9];
    const float* b1    = (const float*)d_in[10];
    const float* Wa    = (const float*)d_in[11];
    const float* ba    = (const float*)d_in[12];
    float* out = (float*)d_out;

    const int T = 256;
    int initBlocks = (NODE_F4 + T - 1) / T;
    unsigned int scatterWork = (unsigned int)N_EDGES * VEC;
    int scatterBlocks = (int)((scatterWork + T - 1) / T);

    // A = emb, acc = A, B = 0
    init_kernel<<<initBlocks, T>>>((const float4*)uemb, (const float4*)iemb);

    // layer 0: A -> B ; acc += B ; zero A
    spmm_scatter<<<scatterBlocks, T>>>(rows, cols, vals, 0);
    addzero_kernel<<<initBlocks, T>>>(0);

    // layer 1: B -> A ; acc += A ; zero B
    spmm_scatter<<<scatterBlocks, T>>>(rows, cols, vals, 1);
    addzero_kernel<<<initBlocks, T>>>(1);

    // layer 2: A -> B ; acc += B
    spmm_scatter<<<scatterBlocks, T>>>(rows, cols, vals, 0);
    addzero_kernel<<<initBlocks, T>>>(0);

    // scoring head
    mlp_kernel<<<BATCH / 8, T>>>(users, items, W0, b0, W1, b1, Wa, ba, out);
}

// round 4
// speedup vs baseline: 1.4452x; 1.4452x over previous
#include <cuda_runtime.h>
#include <math.h>

#define NUM_USERS 100000
#define NUM_ITEMS 50000
#define N_NODES   (NUM_USERS + NUM_ITEMS)   // 150000
#define LATENT    64
#define N_EDGES   2400000
#define BATCH     16384
#define VEC       (LATENT / 4)              // 16 float4 per node row
#define NODE_F4   (N_NODES * VEC)           // 2.4M float4 elements
#define EQ        (N_EDGES / 4)             // 600000 edges per quarter

// Layer outputs (38.4 MB each). Static device globals — allocation-free,
// graph-capture safe. No separate concat/acc buffers: layer-0 gathers from
// the input embeddings, and the MLP sums e0+l1+l2+l3 on the fly.
__device__ float g_L1[N_NODES * LATENT];
__device__ float g_L2[N_NODES * LATENT];
__device__ float g_L3[N_NODES * LATENT];

// ---------------------------------------------------------------------------
// zero3: clear all three layer-output buffers (they are RED destinations).
// Must run every call (graph replays reuse the globals).
// ---------------------------------------------------------------------------
__global__ void zero3_kernel()
{
    int i = blockIdx.x * blockDim.x + threadIdx.x;
    if (i >= NODE_F4) return;
    float4 z = make_float4(0.f, 0.f, 0.f, 0.f);
    ((float4*)g_L1)[i] = z;
    ((float4*)g_L2)[i] = z;
    ((float4*)g_L3)[i] = z;
}

#define REDV4(ptr, s, xv)                                              \
    asm volatile("red.global.add.v4.f32 [%0], {%1, %2, %3, %4};"       \
                 :: "l"(ptr), "f"((s)*(xv).x), "f"((s)*(xv).y),        \
                    "f"((s)*(xv).z), "f"((s)*(xv).w) : "memory")

// ---------------------------------------------------------------------------
// SPMM layer 0: gather straight from the split input embedding tables.
// Each thread processes 4 (edge, float4-chunk) pairs taken from 4 strided
// edge quarters -> 12 metadata loads + 4 gathers issue back-to-back (ILP=4),
// hiding the ~250-cycle L2-hit latency. 16 consecutive threads share an
// edge, so metadata loads broadcast and gathers/REDs are coalesced 256B.
// ---------------------------------------------------------------------------
__global__ void spmm_first(const int*   __restrict__ rows,
                           const int*   __restrict__ cols,
                           const float* __restrict__ vals,
                           const float4* __restrict__ uemb,
                           const float4* __restrict__ iemb)
{
    unsigned int t = blockIdx.x * blockDim.x + threadIdx.x;   // < EQ*VEC
    unsigned int e = t >> 4;
    unsigned int c = t & 15u;
    float4* y = (float4*)g_L1;

    int   r0 = rows[e],          r1 = rows[e + EQ],
          r2 = rows[e + 2*EQ],   r3 = rows[e + 3*EQ];
    int   c0 = cols[e],          c1 = cols[e + EQ],
          c2 = cols[e + 2*EQ],   c3 = cols[e + 3*EQ];
    float v0 = vals[e],          v1 = vals[e + EQ],
          v2 = vals[e + 2*EQ],   v3 = vals[e + 3*EQ];

    const float4* p0 = (c0 < NUM_USERS) ? uemb + c0*VEC : iemb + (c0-NUM_USERS)*VEC;
    const float4* p1 = (c1 < NUM_USERS) ? uemb + c1*VEC : iemb + (c1-NUM_USERS)*VEC;
    const float4* p2 = (c2 < NUM_USERS) ? uemb + c2*VEC : iemb + (c2-NUM_USERS)*VEC;
    const float4* p3 = (c3 < NUM_USERS) ? uemb + c3*VEC : iemb + (c3-NUM_USERS)*VEC;

    float4 x0 = p0[c], x1 = p1[c], x2 = p2[c], x3 = p3[c];

    REDV4(&y[r0*VEC + c], v0, x0);
    REDV4(&y[r1*VEC + c], v1, x1);
    REDV4(&y[r2*VEC + c], v2, x2);
    REDV4(&y[r3*VEC + c], v3, x3);
}

// ---------------------------------------------------------------------------
// SPMM layers 1/2 over the device-global layer buffers.
// dir==0: L1 -> L2 ; dir==1: L2 -> L3
// ---------------------------------------------------------------------------
__global__ void spmm_next(const int*   __restrict__ rows,
                          const int*   __restrict__ cols,
                          const float* __restrict__ vals,
                          int dir)
{
    const float4* __restrict__ x = (const float4*)(dir ? g_L2 : g_L1);
    float4* y = (float4*)(dir ? g_L3 : g_L2);

    unsigned int t = blockIdx.x * blockDim.x + threadIdx.x;   // < EQ*VEC
    unsigned int e = t >> 4;
    unsigned int c = t & 15u;

    int   r0 = rows[e],          r1 = rows[e + EQ],
          r2 = rows[e + 2*EQ],   r3 = rows[e + 3*EQ];
    int   c0 = cols[e],          c1 = cols[e + EQ],
          c2 = cols[e + 2*EQ],   c3 = cols[e + 3*EQ];
    float v0 = vals[e],          v1 = vals[e + EQ],
          v2 = vals[e + 2*EQ],   v3 = vals[e + 3*EQ];

    float4 x0 = x[c0*VEC + c], x1 = x[c1*VEC + c],
           x2 = x[c2*VEC + c], x3 = x[c3*VEC + c];

    REDV4(&y[r0*VEC + c], v0, x0);
    REDV4(&y[r1*VEC + c], v1, x1);
    REDV4(&y[r2*VEC + c], v2, x2);
    REDV4(&y[r3*VEC + c], v3, x3);
}

// ---------------------------------------------------------------------------
// MLP head: one warp per sample.
//   v  = 0.25 * concat(sum_row(user), sum_row(item))        (128)
//        where sum_row(n) = emb[n] + L1[n] + L2[n] + L3[n]
//   h0 = relu(v @ W0 + b0); h1 = relu(h0 @ W1 + b1)
//   out = sigmoid(h1 @ Wa + ba)
// ---------------------------------------------------------------------------
__global__ void mlp_kernel(const int*   __restrict__ users,
                           const int*   __restrict__ items,
                           const float* __restrict__ uemb,
                           const float* __restrict__ iemb,
                           const float* __restrict__ W0,
                           const float* __restrict__ b0,
                           const float* __restrict__ W1,
                           const float* __restrict__ b1,
                           const float* __restrict__ Wa,
                           const float* __restrict__ ba,
                           float* __restrict__ out)
{
    __shared__ float sv[8][128];
    __shared__ float sh0[8][64];

    int w    = threadIdx.x >> 5;
    int lane = threadIdx.x & 31;
    int s    = blockIdx.x * 8 + w;
    if (s >= BATCH) return;

    int u  = users[s];
    int it = items[s];
    int ni = NUM_USERS + it;      // item node id in the layer buffers

    #pragma unroll
    for (int k = lane; k < 64; k += 32) {
        float su = uemb[u * LATENT + k]
                 + g_L1[u * LATENT + k] + g_L2[u * LATENT + k] + g_L3[u * LATENT + k];
        float si = iemb[it * LATENT + k]
                 + g_L1[ni * LATENT + k] + g_L2[ni * LATENT + k] + g_L3[ni * LATENT + k];
        sv[w][k]      = 0.25f * su;
        sv[w][64 + k] = 0.25f * si;
    }
    __syncwarp();

    // layer 0: 128 -> 64, each lane computes outputs {lane, lane+32}
    float a0 = b0[lane];
    float a1 = b0[lane + 32];
    #pragma unroll 8
    for (int k = 0; k < 128; k++) {
        float vk = sv[w][k];
        a0 = fmaf(vk, W0[k * 64 + lane],      a0);
        a1 = fmaf(vk, W0[k * 64 + lane + 32], a1);
    }
    sh0[w][lane]      = fmaxf(a0, 0.f);
    sh0[w][lane + 32] = fmaxf(a1, 0.f);
    __syncwarp();

    // layer 1: 64 -> 32
    float h1 = b1[lane];
    #pragma unroll 8
    for (int k = 0; k < 64; k++)
        h1 = fmaf(sh0[w][k], W1[k * 32 + lane], h1);
    h1 = fmaxf(h1, 0.f);

    // logit + sigmoid
    float tsum = h1 * Wa[lane];
    #pragma unroll
    for (int off = 16; off > 0; off >>= 1)
        tsum += __shfl_down_sync(0xffffffffu, tsum, off);

    if (lane == 0) {
        float logit = tsum + ba[0];
        out[s] = 1.0f / (1.0f + __expf(-logit));
    }
}

// ---------------------------------------------------------------------------
extern "C" void kernel_launch(void* const* d_in, const int* in_sizes, int n_in,
                              void* d_out, int out_size)
{
    const int*   users = (const int*)  d_in[0];
    const int*   items = (const int*)  d_in[1];
    const int*   rows  = (const int*)  d_in[2];
    const int*   cols  = (const int*)  d_in[3];
    const float* vals  = (const float*)d_in[4];
    const float* uemb  = (const float*)d_in[5];
    const float* iemb  = (const float*)d_in[6];
    const float* W0    = (const float*)d_in[7];
    const float* b0    = (const float*)d_in[8];
    const float* W1    = (const float*)d_in[9];
    const float* b1    = (const float*)d_in[10];
    const float* Wa    = (const float*)d_in[11];
    const float* ba    = (const float*)d_in[12];
    float* out = (float*)d_out;

    const int T = 256;
    int zeroBlocks = (NODE_F4 + T - 1) / T;
    // EQ*VEC = 9.6M threads, exactly divisible by 256
    int spmmBlocks = (EQ * VEC) / T;

    zero3_kernel<<<zeroBlocks, T>>>();

    spmm_first<<<spmmBlocks, T>>>(rows, cols, vals,
                                  (const float4*)uemb, (const float4*)iemb);
    spmm_next<<<spmmBlocks, T>>>(rows, cols, vals, 0);
    spmm_next<<<spmmBlocks, T>>>(rows, cols, vals, 1);

    mlp_kernel<<<BATCH / 8, T>>>(users, items, uemb, iemb,
                                 W0, b0, W1, b1, Wa, ba, out);
}